// round 4
// baseline (speedup 1.0000x reference)
#include <cuda_runtime.h>
#include <cuda_bf16.h>
#include <cstddef>

#define BATCH 64
#define LSEQ 784
#define HDIM 512
#define NSTATE 64
#define NLAYERS 6

// -------- scratch (no allocations allowed) --------
__device__ float g_h[(size_t)BATCH * HDIM * LSEQ];   // activations, (B,H,L)
__device__ float g_y[(size_t)BATCH * HDIM * LSEQ];   // conv output, (B,H,L)
__device__ float g_wr[NLAYERS * HDIM * NSTATE];
__device__ float g_wi[NLAYERS * HDIM * NSTATE];
__device__ float g_cr[NLAYERS * HDIM * NSTATE];
__device__ float g_ci[NLAYERS * HDIM * NSTATE];

// -------- precompute discretized SSM params --------
__global__ void precompute_kernel(const float* __restrict__ log_dt,
                                  const float* __restrict__ log_A_real,
                                  const float* __restrict__ A_imag,
                                  const float* __restrict__ C_re,
                                  const float* __restrict__ C_im) {
    int idx = blockIdx.x * blockDim.x + threadIdx.x;
    if (idx >= NLAYERS * HDIM * NSTATE) return;
    int hh = (idx / NSTATE) % HDIM;
    int i = idx / (NSTATE * HDIM);
    float dt = expf(log_dt[i * HDIM + hh]);
    float Ar = -expf(log_A_real[idx]);
    float Ai = A_imag[idx];
    float xr = Ar * dt, xi = Ai * dt;
    float e = expf(xr);
    float wre = e * cosf(xi), wim = e * sinf(xi);
    // Cd = C * (exp(dtA)-1) / A
    float em1r = wre - 1.0f, em1i = wim;
    float Cre = C_re[idx], Cim = C_im[idx];
    float tr = Cre * em1r - Cim * em1i;
    float ti = Cre * em1i + Cim * em1r;
    float den = Ar * Ar + Ai * Ai;
    float inv = 1.0f / den;
    g_wr[idx] = wre; g_wi[idx] = wim;
    g_cr[idx] = (tr * Ar + ti * Ai) * inv;
    g_ci[idx] = (ti * Ar - tr * Ai) * inv;
}

// -------- encoder: h[b,h,l] = x[b,l]*enc_w[h] + enc_b[h] --------
__global__ void __launch_bounds__(256) encoder_kernel(const float* __restrict__ x,
                                                      const float* __restrict__ enc_w,
                                                      const float* __restrict__ enc_b) {
    int pair = blockIdx.x;            // b*HDIM + h
    int b = pair >> 9, h = pair & 511;
    float w = enc_w[h], bb = enc_b[h];
    const float* xr = x + (size_t)b * LSEQ;
    float* hr = g_h + (size_t)pair * LSEQ;
    for (int l = threadIdx.x; l < LSEQ; l += 256)
        hr[l] = fmaf(xr[l], w, bb);
}

// -------- S4D conv via diagonal recurrence --------
// 8 lanes per (b,h) pair, 8 states per lane, 4 pairs per warp, 4 warps per block.
#define CH 112
#define CHP 116

__global__ void __launch_bounds__(128) conv_kernel(const float* __restrict__ Dvec, int layer) {
    __shared__ float shu[16][CHP];
    __shared__ float shy[16][CHP];
    int tid = threadIdx.x;
    int warp = tid >> 5, lane = tid & 31;
    int g = lane >> 3;         // group 0..3
    int lg = lane & 7;         // lane in group
    int pairLocal = warp * 4 + g;                 // 0..15
    int pair = blockIdx.x * 16 + pairLocal;       // b*HDIM + h
    int h = pair & 511;
    const float* urow = g_h + (size_t)pair * LSEQ;
    float* yrow = g_y + (size_t)pair * LSEQ;
    int pbase = (layer * HDIM + h) * NSTATE;

    float swr[8], swi[8], scr[8], sci[8], sre[8], sim[8];
#pragma unroll
    for (int j = 0; j < 8; j++) {
        int n = lg + 8 * j;
        swr[j] = g_wr[pbase + n]; swi[j] = g_wi[pbase + n];
        scr[j] = g_cr[pbase + n]; sci[j] = g_ci[pbase + n];
        sre[j] = 0.0f; sim[j] = 0.0f;
    }
    float Dh = Dvec[layer * HDIM + h];

    for (int c0 = 0; c0 < LSEQ; c0 += CH) {
#pragma unroll
        for (int k = 0; k < CH / 8; k++)
            shu[pairLocal][lg + 8 * k] = urow[c0 + lg + 8 * k];
        __syncwarp();
#pragma unroll 4
        for (int l = 0; l < CH; l++) {
            float uv = shu[pairLocal][l];
            float acc = 0.0f;
#pragma unroll
            for (int j = 0; j < 8; j++) {
                float nr = fmaf(swr[j], sre[j], fmaf(-swi[j], sim[j], uv));
                float ni = fmaf(swr[j], sim[j], swi[j] * sre[j]);
                sre[j] = nr; sim[j] = ni;
                acc = fmaf(scr[j], nr, acc);
                acc = fmaf(-sci[j], ni, acc);
            }
            acc += __shfl_xor_sync(0xffffffffu, acc, 1, 8);
            acc += __shfl_xor_sync(0xffffffffu, acc, 2, 8);
            acc += __shfl_xor_sync(0xffffffffu, acc, 4, 8);
            if (lg == 0) shy[pairLocal][l] = fmaf(2.0f, acc, Dh * uv);
        }
        __syncwarp();
#pragma unroll
        for (int k = 0; k < CH / 8; k++)
            yrow[c0 + lg + 8 * k] = shy[pairLocal][lg + 8 * k];
        __syncwarp();
    }
}

// -------- residual + layernorm over H, (B,H,L) layout --------
// grid: (L/16, B), block: 512 = 16 l-lanes x 32 h-threads
__global__ void __launch_bounds__(512) ln_kernel(const float* __restrict__ gamma,
                                                 const float* __restrict__ beta,
                                                 int addY) {
    int b = blockIdx.y;
    int l0 = blockIdx.x * 16;
    int lx = threadIdx.x & 15;
    int hy = threadIdx.x >> 4;
    __shared__ float z[HDIM][16];
    __shared__ float s1s[32][16], s2s[32][16];
    __shared__ float smean[16], srstd[16];
    float s1 = 0.0f, s2 = 0.0f;
    for (int h = hy; h < HDIM; h += 32) {
        size_t off = ((size_t)(b * HDIM + h)) * LSEQ + l0 + lx;
        float v = g_h[off];
        if (addY) v += g_y[off];
        z[h][lx] = v;
        s1 += v; s2 += v * v;
    }
    s1s[hy][lx] = s1; s2s[hy][lx] = s2;
    __syncthreads();
    for (int st = 16; st >= 1; st >>= 1) {
        if (hy < st) { s1s[hy][lx] += s1s[hy + st][lx]; s2s[hy][lx] += s2s[hy + st][lx]; }
        __syncthreads();
    }
    if (hy == 0) {
        float mean = s1s[0][lx] * (1.0f / HDIM);
        float var = s2s[0][lx] * (1.0f / HDIM) - mean * mean;
        smean[lx] = mean;
        srstd[lx] = rsqrtf(var + 1e-5f);
    }
    __syncthreads();
    float mean = smean[lx], rstd = srstd[lx];
    for (int h = hy; h < HDIM; h += 32) {
        size_t off = ((size_t)(b * HDIM + h)) * LSEQ + l0 + lx;
        g_h[off] = (z[h][lx] - mean) * rstd * gamma[h] + beta[h];
    }
}

// -------- mean-pool over L + decode to 10 classes --------
__global__ void __launch_bounds__(256) pool_decode_kernel(const float* __restrict__ dec_w,
                                                          const float* __restrict__ dec_b,
                                                          float* __restrict__ out) {
    int b = blockIdx.x;
    int t = threadIdx.x;
    __shared__ float pooled[HDIM];
    for (int h = t; h < HDIM; h += 256) {
        const float4* row = (const float4*)(g_h + ((size_t)(b * HDIM + h)) * LSEQ);
        float s = 0.0f;
        for (int l = 0; l < LSEQ / 4; l++) {
            float4 v = row[l];
            s += (v.x + v.y) + (v.z + v.w);
        }
        pooled[h] = s * (1.0f / LSEQ);
    }
    __syncthreads();
    float acc[10];
#pragma unroll
    for (int k = 0; k < 10; k++) acc[k] = 0.0f;
    for (int h = t; h < HDIM; h += 256) {
        float p = pooled[h];
#pragma unroll
        for (int k = 0; k < 10; k++) acc[k] = fmaf(p, dec_w[h * 10 + k], acc[k]);
    }
    __shared__ float red[256];
    for (int k = 0; k < 10; k++) {
        red[t] = acc[k];
        __syncthreads();
        for (int st = 128; st >= 1; st >>= 1) {
            if (t < st) red[t] += red[t + st];
            __syncthreads();
        }
        if (t == 0) out[b * 10 + k] = red[0] + dec_b[k];
        __syncthreads();
    }
}

extern "C" void kernel_launch(void* const* d_in, const int* in_sizes, int n_in,
                              void* d_out, int out_size) {
    const float* x          = (const float*)d_in[0];
    const float* enc_w      = (const float*)d_in[1];
    const float* enc_b      = (const float*)d_in[2];
    const float* log_dt     = (const float*)d_in[3];
    const float* log_A_real = (const float*)d_in[4];
    const float* A_imag     = (const float*)d_in[5];
    const float* C_re       = (const float*)d_in[6];
    const float* C_im       = (const float*)d_in[7];
    const float* Dvec       = (const float*)d_in[8];
    const float* ln_g       = (const float*)d_in[9];
    const float* ln_b       = (const float*)d_in[10];
    const float* fn_g       = (const float*)d_in[11];
    const float* fn_b       = (const float*)d_in[12];
    const float* dec_w      = (const float*)d_in[13];
    const float* dec_b      = (const float*)d_in[14];
    float* out = (float*)d_out;

    int np = NLAYERS * HDIM * NSTATE;
    precompute_kernel<<<(np + 255) / 256, 256>>>(log_dt, log_A_real, A_imag, C_re, C_im);
    encoder_kernel<<<BATCH * HDIM, 256>>>(x, enc_w, enc_b);

    for (int i = 0; i < NLAYERS; i++) {
        conv_kernel<<<(BATCH * HDIM) / 16, 128>>>(Dvec, i);
        ln_kernel<<<dim3(LSEQ / 16, BATCH), 512>>>(ln_g + i * HDIM, ln_b + i * HDIM, 1);
    }
    ln_kernel<<<dim3(LSEQ / 16, BATCH), 512>>>(fn_g, fn_b, 0);
    pool_decode_kernel<<<BATCH, 256>>>(dec_w, dec_b, out);
}

// round 5
// speedup vs baseline: 1.0005x; 1.0005x over previous
#include <cuda_runtime.h>
#include <cuda_bf16.h>
#include <cstddef>

#define BATCH 64
#define LSEQ 784
#define HDIM 512
#define NSTATE 64
#define NLAYERS 6

// -------- scratch (no allocations allowed) --------
__device__ float g_h[(size_t)BATCH * HDIM * LSEQ];   // activations, (B,H,L)
__device__ float g_y[(size_t)BATCH * HDIM * LSEQ];   // conv output, (B,H,L)
__device__ float g_wr[NLAYERS * HDIM * NSTATE];
__device__ float g_wi[NLAYERS * HDIM * NSTATE];
__device__ float g_cr[NLAYERS * HDIM * NSTATE];
__device__ float g_ci[NLAYERS * HDIM * NSTATE];

// -------- precompute discretized SSM params --------
__global__ void precompute_kernel(const float* __restrict__ log_dt,
                                  const float* __restrict__ log_A_real,
                                  const float* __restrict__ A_imag,
                                  const float* __restrict__ C_re,
                                  const float* __restrict__ C_im) {
    int idx = blockIdx.x * blockDim.x + threadIdx.x;
    if (idx >= NLAYERS * HDIM * NSTATE) return;
    int hh = (idx / NSTATE) % HDIM;
    int i = idx / (NSTATE * HDIM);
    float dt = expf(log_dt[i * HDIM + hh]);
    float Ar = -expf(log_A_real[idx]);
    float Ai = A_imag[idx];
    float xr = Ar * dt, xi = Ai * dt;
    float e = expf(xr);
    float wre = e * cosf(xi), wim = e * sinf(xi);
    // Cd = C * (exp(dtA)-1) / A
    float em1r = wre - 1.0f, em1i = wim;
    float Cre = C_re[idx], Cim = C_im[idx];
    float tr = Cre * em1r - Cim * em1i;
    float ti = Cre * em1i + Cim * em1r;
    float den = Ar * Ar + Ai * Ai;
    float inv = 1.0f / den;
    g_wr[idx] = wre; g_wi[idx] = wim;
    g_cr[idx] = (tr * Ar + ti * Ai) * inv;
    g_ci[idx] = (ti * Ar - tr * Ai) * inv;
}

// -------- encoder: h[b,h,l] = x[b,l]*enc_w[h] + enc_b[h] --------
__global__ void __launch_bounds__(256) encoder_kernel(const float* __restrict__ x,
                                                      const float* __restrict__ enc_w,
                                                      const float* __restrict__ enc_b) {
    int pair = blockIdx.x;            // b*HDIM + h
    int b = pair >> 9, h = pair & 511;
    float w = enc_w[h], bb = enc_b[h];
    const float* xr = x + (size_t)b * LSEQ;
    float* hr = g_h + (size_t)pair * LSEQ;
    for (int l = threadIdx.x; l < LSEQ; l += 256)
        hr[l] = fmaf(xr[l], w, bb);
}

// -------- S4D conv via diagonal recurrence --------
// 8 lanes per (b,h) pair, 8 states per lane, 4 pairs per warp, 4 warps per block.
#define CH 112
#define CHP 116

__global__ void __launch_bounds__(128) conv_kernel(const float* __restrict__ Dvec, int layer) {
    __shared__ float shu[16][CHP];
    __shared__ float shy[16][CHP];
    int tid = threadIdx.x;
    int warp = tid >> 5, lane = tid & 31;
    int g = lane >> 3;         // group 0..3
    int lg = lane & 7;         // lane in group
    int pairLocal = warp * 4 + g;                 // 0..15
    int pair = blockIdx.x * 16 + pairLocal;       // b*HDIM + h
    int h = pair & 511;
    const float* urow = g_h + (size_t)pair * LSEQ;
    float* yrow = g_y + (size_t)pair * LSEQ;
    int pbase = (layer * HDIM + h) * NSTATE;

    float swr[8], swi[8], scr[8], sci[8], sre[8], sim[8];
#pragma unroll
    for (int j = 0; j < 8; j++) {
        int n = lg + 8 * j;
        swr[j] = g_wr[pbase + n]; swi[j] = g_wi[pbase + n];
        scr[j] = g_cr[pbase + n]; sci[j] = g_ci[pbase + n];
        sre[j] = 0.0f; sim[j] = 0.0f;
    }
    float Dh = Dvec[layer * HDIM + h];

    for (int c0 = 0; c0 < LSEQ; c0 += CH) {
#pragma unroll
        for (int k = 0; k < CH / 8; k++)
            shu[pairLocal][lg + 8 * k] = urow[c0 + lg + 8 * k];
        __syncwarp();
#pragma unroll 4
        for (int l = 0; l < CH; l++) {
            float uv = shu[pairLocal][l];
            float acc = 0.0f;
#pragma unroll
            for (int j = 0; j < 8; j++) {
                float nr = fmaf(swr[j], sre[j], fmaf(-swi[j], sim[j], uv));
                float ni = fmaf(swr[j], sim[j], swi[j] * sre[j]);
                sre[j] = nr; sim[j] = ni;
                acc = fmaf(scr[j], nr, acc);
                acc = fmaf(-sci[j], ni, acc);
            }
            acc += __shfl_xor_sync(0xffffffffu, acc, 1, 8);
            acc += __shfl_xor_sync(0xffffffffu, acc, 2, 8);
            acc += __shfl_xor_sync(0xffffffffu, acc, 4, 8);
            if (lg == 0) shy[pairLocal][l] = fmaf(2.0f, acc, Dh * uv);
        }
        __syncwarp();
#pragma unroll
        for (int k = 0; k < CH / 8; k++)
            yrow[c0 + lg + 8 * k] = shy[pairLocal][lg + 8 * k];
        __syncwarp();
    }
}

// -------- residual + layernorm over H, (B,H,L) layout --------
// grid: (L/16, B), block: 512 = 16 l-lanes x 32 h-threads
__global__ void __launch_bounds__(512) ln_kernel(const float* __restrict__ gamma,
                                                 const float* __restrict__ beta,
                                                 int addY) {
    int b = blockIdx.y;
    int l0 = blockIdx.x * 16;
    int lx = threadIdx.x & 15;
    int hy = threadIdx.x >> 4;
    __shared__ float z[HDIM][16];
    __shared__ float s1s[32][16], s2s[32][16];
    __shared__ float smean[16], srstd[16];
    float s1 = 0.0f, s2 = 0.0f;
    for (int h = hy; h < HDIM; h += 32) {
        size_t off = ((size_t)(b * HDIM + h)) * LSEQ + l0 + lx;
        float v = g_h[off];
        if (addY) v += g_y[off];
        z[h][lx] = v;
        s1 += v; s2 += v * v;
    }
    s1s[hy][lx] = s1; s2s[hy][lx] = s2;
    __syncthreads();
    for (int st = 16; st >= 1; st >>= 1) {
        if (hy < st) { s1s[hy][lx] += s1s[hy + st][lx]; s2s[hy][lx] += s2s[hy + st][lx]; }
        __syncthreads();
    }
    if (hy == 0) {
        float mean = s1s[0][lx] * (1.0f / HDIM);
        float var = s2s[0][lx] * (1.0f / HDIM) - mean * mean;
        smean[lx] = mean;
        srstd[lx] = rsqrtf(var + 1e-5f);
    }
    __syncthreads();
    float mean = smean[lx], rstd = srstd[lx];
    for (int h = hy; h < HDIM; h += 32) {
        size_t off = ((size_t)(b * HDIM + h)) * LSEQ + l0 + lx;
        g_h[off] = (z[h][lx] - mean) * rstd * gamma[h] + beta[h];
    }
}

// -------- mean-pool over L + decode to 10 classes --------
__global__ void __launch_bounds__(256) pool_decode_kernel(const float* __restrict__ dec_w,
                                                          const float* __restrict__ dec_b,
                                                          float* __restrict__ out) {
    int b = blockIdx.x;
    int t = threadIdx.x;
    __shared__ float pooled[HDIM];
    for (int h = t; h < HDIM; h += 256) {
        const float4* row = (const float4*)(g_h + ((size_t)(b * HDIM + h)) * LSEQ);
        float s = 0.0f;
        for (int l = 0; l < LSEQ / 4; l++) {
            float4 v = row[l];
            s += (v.x + v.y) + (v.z + v.w);
        }
        pooled[h] = s * (1.0f / LSEQ);
    }
    __syncthreads();
    float acc[10];
#pragma unroll
    for (int k = 0; k < 10; k++) acc[k] = 0.0f;
    for (int h = t; h < HDIM; h += 256) {
        float p = pooled[h];
#pragma unroll
        for (int k = 0; k < 10; k++) acc[k] = fmaf(p, dec_w[h * 10 + k], acc[k]);
    }
    __shared__ float red[256];
    for (int k = 0; k < 10; k++) {
        red[t] = acc[k];
        __syncthreads();
        for (int st = 128; st >= 1; st >>= 1) {
            if (t < st) red[t] += red[t + st];
            __syncthreads();
        }
        if (t == 0) out[b * 10 + k] = red[0] + dec_b[k];
        __syncthreads();
    }
}

extern "C" void kernel_launch(void* const* d_in, const int* in_sizes, int n_in,
                              void* d_out, int out_size) {
    const float* x          = (const float*)d_in[0];
    const float* enc_w      = (const float*)d_in[1];
    const float* enc_b      = (const float*)d_in[2];
    const float* log_dt     = (const float*)d_in[3];
    const float* log_A_real = (const float*)d_in[4];
    const float* A_imag     = (const float*)d_in[5];
    const float* C_re       = (const float*)d_in[6];
    const float* C_im       = (const float*)d_in[7];
    const float* Dvec       = (const float*)d_in[8];
    const float* ln_g       = (const float*)d_in[9];
    const float* ln_b       = (const float*)d_in[10];
    const float* fn_g       = (const float*)d_in[11];
    const float* fn_b       = (const float*)d_in[12];
    const float* dec_w      = (const float*)d_in[13];
    const float* dec_b      = (const float*)d_in[14];
    float* out = (float*)d_out;

    int np = NLAYERS * HDIM * NSTATE;
    precompute_kernel<<<(np + 255) / 256, 256>>>(log_dt, log_A_real, A_imag, C_re, C_im);
    encoder_kernel<<<BATCH * HDIM, 256>>>(x, enc_w, enc_b);

    for (int i = 0; i < NLAYERS; i++) {
        conv_kernel<<<(BATCH * HDIM) / 16, 128>>>(Dvec, i);
        ln_kernel<<<dim3(LSEQ / 16, BATCH), 512>>>(ln_g + i * HDIM, ln_b + i * HDIM, 1);
    }
    ln_kernel<<<dim3(LSEQ / 16, BATCH), 512>>>(fn_g, fn_b, 0);
    pool_decode_kernel<<<BATCH, 256>>>(dec_w, dec_b, out);
}

// round 6
// speedup vs baseline: 1.0283x; 1.0278x over previous
#include <cuda_runtime.h>
#include <cuda_bf16.h>
#include <cstddef>

#define BATCH 64
#define LSEQ 784
#define HDIM 512
#define NSTATE 64
#define NLAYERS 6

// -------- scratch (no allocations allowed) --------
__device__ float g_h[(size_t)BATCH * HDIM * LSEQ];   // activations, (B,H,L)
__device__ float g_y[(size_t)BATCH * HDIM * LSEQ];   // z = h + conv(h), (B,H,L)
__device__ float g_wr[NLAYERS * HDIM * NSTATE];
__device__ float g_wi[NLAYERS * HDIM * NSTATE];
__device__ float g_cr[NLAYERS * HDIM * NSTATE];
__device__ float g_ci[NLAYERS * HDIM * NSTATE];

// -------- packed f32x2 helpers (Blackwell FFMA2) --------
typedef unsigned long long u64;
__device__ __forceinline__ u64 f2pk(float lo, float hi) {
    u64 r; asm("mov.b64 %0, {%1, %2};" : "=l"(r) : "f"(lo), "f"(hi)); return r;
}
__device__ __forceinline__ void f2un(u64 v, float& lo, float& hi) {
    asm("mov.b64 {%0, %1}, %2;" : "=f"(lo), "=f"(hi) : "l"(v));
}
__device__ __forceinline__ u64 ffma2(u64 a, u64 b, u64 c) {
    u64 d; asm("fma.rn.f32x2 %0, %1, %2, %3;" : "=l"(d) : "l"(a), "l"(b), "l"(c)); return d;
}
__device__ __forceinline__ u64 fmul2(u64 a, u64 b) {
    u64 d; asm("mul.rn.f32x2 %0, %1, %2;" : "=l"(d) : "l"(a), "l"(b)); return d;
}

// -------- precompute discretized SSM params --------
__global__ void precompute_kernel(const float* __restrict__ log_dt,
                                  const float* __restrict__ log_A_real,
                                  const float* __restrict__ A_imag,
                                  const float* __restrict__ C_re,
                                  const float* __restrict__ C_im) {
    int idx = blockIdx.x * blockDim.x + threadIdx.x;
    if (idx >= NLAYERS * HDIM * NSTATE) return;
    int hh = (idx / NSTATE) % HDIM;
    int i = idx / (NSTATE * HDIM);
    float dt = expf(log_dt[i * HDIM + hh]);
    float Ar = -expf(log_A_real[idx]);
    float Ai = A_imag[idx];
    float xr = Ar * dt, xi = Ai * dt;
    float e = expf(xr);
    float wre = e * cosf(xi), wim = e * sinf(xi);
    // Cd = C * (exp(dtA)-1) / A
    float em1r = wre - 1.0f, em1i = wim;
    float Cre = C_re[idx], Cim = C_im[idx];
    float tr = Cre * em1r - Cim * em1i;
    float ti = Cre * em1i + Cim * em1r;
    float den = Ar * Ar + Ai * Ai;
    float inv = 1.0f / den;
    g_wr[idx] = wre; g_wi[idx] = wim;
    g_cr[idx] = (tr * Ar + ti * Ai) * inv;
    g_ci[idx] = (ti * Ar - tr * Ai) * inv;
}

// -------- encoder: h[b,h,l] = x[b,l]*enc_w[h] + enc_b[h] --------
__global__ void __launch_bounds__(256) encoder_kernel(const float* __restrict__ x,
                                                      const float* __restrict__ enc_w,
                                                      const float* __restrict__ enc_b) {
    int pair = blockIdx.x;            // b*HDIM + h
    int b = pair >> 9, h = pair & 511;
    float w = enc_w[h], bb = enc_b[h];
    const float* xr = x + (size_t)b * LSEQ;
    float* hr = g_h + (size_t)pair * LSEQ;
    for (int l = threadIdx.x; l < LSEQ; l += 256)
        hr[l] = fmaf(xr[l], w, bb);
}

// -------- S4D conv via diagonal recurrence, f32x2-packed --------
// 8 lanes per (b,h) pair, 8 states per lane (4 f32x2 pairs), 4 pairs per warp.
#define CH 112
#define CHP 116

__global__ void __launch_bounds__(128) conv_kernel(const float* __restrict__ Dvec, int layer) {
    __shared__ float shu[16][CHP];
    __shared__ float shy[16][CHP];
    int tid = threadIdx.x;
    int warp = tid >> 5, lane = tid & 31;
    int g = lane >> 3;         // group 0..3
    int lg = lane & 7;         // lane in group
    int pairLocal = warp * 4 + g;                 // 0..15
    int pair = blockIdx.x * 16 + pairLocal;       // b*HDIM + h
    int h = pair & 511;
    const float* urow = g_h + (size_t)pair * LSEQ;
    float* zrow = g_y + (size_t)pair * LSEQ;
    int pbase = (layer * HDIM + h) * NSTATE;

    // packed params: pair (state 2j, state 2j+1) per 64-bit register
    u64 pwr[4], pwi[4], pwin[4], pcr[4], pcin[4], pre[4], pim[4];
#pragma unroll
    for (int j = 0; j < 4; j++) {
        int nlo = lg + 8 * (2 * j);
        int nhi = lg + 8 * (2 * j + 1);
        float wrl = g_wr[pbase + nlo], wrh = g_wr[pbase + nhi];
        float wil = g_wi[pbase + nlo], wih = g_wi[pbase + nhi];
        float crl = g_cr[pbase + nlo], crh = g_cr[pbase + nhi];
        float cil = g_ci[pbase + nlo], cih = g_ci[pbase + nhi];
        pwr[j]  = f2pk(wrl, wrh);
        pwi[j]  = f2pk(wil, wih);
        pwin[j] = f2pk(-wil, -wih);
        pcr[j]  = f2pk(crl, crh);
        pcin[j] = f2pk(-cil, -cih);
        pre[j] = 0ull; pim[j] = 0ull;
    }
    float Dh = Dvec[layer * HDIM + h];
    float D1 = 1.0f + Dh;

    for (int c0 = 0; c0 < LSEQ; c0 += CH) {
#pragma unroll
        for (int k = 0; k < CH / 8; k++)
            shu[pairLocal][lg + 8 * k] = urow[c0 + lg + 8 * k];
        __syncwarp();
#pragma unroll 4
        for (int l = 0; l < CH; l++) {
            float uv = shu[pairLocal][l];
            u64 uv2 = f2pk(uv, uv);
            u64 acc2 = 0ull;
#pragma unroll
            for (int j = 0; j < 4; j++) {
                u64 t  = ffma2(pwin[j], pim[j], uv2);      // uv - wi*sim
                u64 nr = ffma2(pwr[j], pre[j], t);         // wr*sre + t
                u64 s  = fmul2(pwi[j], pre[j]);            // wi*sre
                u64 ni = ffma2(pwr[j], pim[j], s);         // wr*sim + s
                pre[j] = nr; pim[j] = ni;
                acc2 = ffma2(pcr[j], nr, acc2);
                acc2 = ffma2(pcin[j], ni, acc2);
            }
            float alo, ahi; f2un(acc2, alo, ahi);
            float acc = alo + ahi;
            acc += __shfl_xor_sync(0xffffffffu, acc, 1, 8);
            acc += __shfl_xor_sync(0xffffffffu, acc, 2, 8);
            acc += __shfl_xor_sync(0xffffffffu, acc, 4, 8);
            if (lg == 0) shy[pairLocal][l] = fmaf(2.0f, acc, D1 * uv);  // z = u + y
        }
        __syncwarp();
#pragma unroll
        for (int k = 0; k < CH / 8; k++)
            zrow[c0 + lg + 8 * k] = shy[pairLocal][lg + 8 * k];
        __syncwarp();
    }
}

// -------- layernorm over H, (B,H,L) layout --------
// addY=1: normalize z (pre-added in conv) from g_y; addY=0: normalize g_h.
// grid: (L/16, B), block: 512 = 16 l-lanes x 32 h-threads
__global__ void __launch_bounds__(512) ln_kernel(const float* __restrict__ gamma,
                                                 const float* __restrict__ beta,
                                                 int addY) {
    int b = blockIdx.y;
    int l0 = blockIdx.x * 16;
    int lx = threadIdx.x & 15;
    int hy = threadIdx.x >> 4;
    __shared__ float z[HDIM][16];
    __shared__ float s1s[32][16], s2s[32][16];
    __shared__ float smean[16], srstd[16];
    const float* src = addY ? g_y : g_h;
    float s1 = 0.0f, s2 = 0.0f;
    for (int h = hy; h < HDIM; h += 32) {
        size_t off = ((size_t)(b * HDIM + h)) * LSEQ + l0 + lx;
        float v = src[off];
        z[h][lx] = v;
        s1 += v; s2 += v * v;
    }
    s1s[hy][lx] = s1; s2s[hy][lx] = s2;
    __syncthreads();
    for (int st = 16; st >= 1; st >>= 1) {
        if (hy < st) { s1s[hy][lx] += s1s[hy + st][lx]; s2s[hy][lx] += s2s[hy + st][lx]; }
        __syncthreads();
    }
    if (hy == 0) {
        float mean = s1s[0][lx] * (1.0f / HDIM);
        float var = s2s[0][lx] * (1.0f / HDIM) - mean * mean;
        smean[lx] = mean;
        srstd[lx] = rsqrtf(var + 1e-5f);
    }
    __syncthreads();
    float mean = smean[lx], rstd = srstd[lx];
    for (int h = hy; h < HDIM; h += 32) {
        size_t off = ((size_t)(b * HDIM + h)) * LSEQ + l0 + lx;
        g_h[off] = (z[h][lx] - mean) * rstd * gamma[h] + beta[h];
    }
}

// -------- mean-pool over L + decode to 10 classes --------
__global__ void __launch_bounds__(256) pool_decode_kernel(const float* __restrict__ dec_w,
                                                          const float* __restrict__ dec_b,
                                                          float* __restrict__ out) {
    int b = blockIdx.x;
    int t = threadIdx.x;
    __shared__ float pooled[HDIM];
    for (int h = t; h < HDIM; h += 256) {
        const float4* row = (const float4*)(g_h + ((size_t)(b * HDIM + h)) * LSEQ);
        float s = 0.0f;
        for (int l = 0; l < LSEQ / 4; l++) {
            float4 v = row[l];
            s += (v.x + v.y) + (v.z + v.w);
        }
        pooled[h] = s * (1.0f / LSEQ);
    }
    __syncthreads();
    float acc[10];
#pragma unroll
    for (int k = 0; k < 10; k++) acc[k] = 0.0f;
    for (int h = t; h < HDIM; h += 256) {
        float p = pooled[h];
#pragma unroll
        for (int k = 0; k < 10; k++) acc[k] = fmaf(p, dec_w[h * 10 + k], acc[k]);
    }
    __shared__ float red[256];
    for (int k = 0; k < 10; k++) {
        red[t] = acc[k];
        __syncthreads();
        for (int st = 128; st >= 1; st >>= 1) {
            if (t < st) red[t] += red[t + st];
            __syncthreads();
        }
        if (t == 0) out[b * 10 + k] = red[0] + dec_b[k];
        __syncthreads();
    }
}

extern "C" void kernel_launch(void* const* d_in, const int* in_sizes, int n_in,
                              void* d_out, int out_size) {
    const float* x          = (const float*)d_in[0];
    const float* enc_w      = (const float*)d_in[1];
    const float* enc_b      = (const float*)d_in[2];
    const float* log_dt     = (const float*)d_in[3];
    const float* log_A_real = (const float*)d_in[4];
    const float* A_imag     = (const float*)d_in[5];
    const float* C_re       = (const float*)d_in[6];
    const float* C_im       = (const float*)d_in[7];
    const float* Dvec       = (const float*)d_in[8];
    const float* ln_g       = (const float*)d_in[9];
    const float* ln_b       = (const float*)d_in[10];
    const float* fn_g       = (const float*)d_in[11];
    const float* fn_b       = (const float*)d_in[12];
    const float* dec_w      = (const float*)d_in[13];
    const float* dec_b      = (const float*)d_in[14];
    float* out = (float*)d_out;

    int np = NLAYERS * HDIM * NSTATE;
    precompute_kernel<<<(np + 255) / 256, 256>>>(log_dt, log_A_real, A_imag, C_re, C_im);
    encoder_kernel<<<BATCH * HDIM, 256>>>(x, enc_w, enc_b);

    for (int i = 0; i < NLAYERS; i++) {
        conv_kernel<<<(BATCH * HDIM) / 16, 128>>>(Dvec, i);
        ln_kernel<<<dim3(LSEQ / 16, BATCH), 512>>>(ln_g + i * HDIM, ln_b + i * HDIM, 1);
    }
    ln_kernel<<<dim3(LSEQ / 16, BATCH), 512>>>(fn_g, fn_b, 0);
    pool_decode_kernel<<<BATCH, 256>>>(dec_w, dec_b, out);
}